// round 1
// baseline (speedup 1.0000x reference)
#include <cuda_runtime.h>

// Problem constants (match reference setup_inputs)
#define DD      256
#define NNODES  50000
#define NEDGES  300000

// Scratch: precomputed node projections [NNODES, 512]
//   proj[n, 0:256]   = node_feat[n,:] @ W[256:512, :]   (src part)
//   proj[n, 256:512] = node_feat[n,:] @ W[512:768, :]   (tgt part)
__device__ float g_proj[(size_t)NNODES * 512];

#define BM 128
#define BN 128
#define BK 8

// ---------------------------------------------------------------------------
// Kernel A: node projection GEMM. M=50000, N=512, K=256.
// B(k, j) = W[(wbase + k)*256 + (j & 255)], wbase = 256 or 512 per column half.
// Column blocks are 128 wide so wbase is uniform per block.
// ---------------------------------------------------------------------------
__global__ __launch_bounds__(256) void node_proj_kernel(
    const float* __restrict__ node, const float* __restrict__ W)
{
    __shared__ float As[BK][BM];
    __shared__ float Bs[BK][BN];

    const int tid = threadIdx.x;
    const int m0  = blockIdx.y * BM;
    const int n0  = blockIdx.x * BN;              // 0, 128, 256, 384
    const int wbase = (n0 < 256) ? 256 : 512;     // W row base
    const int jcol  = n0 & 255;                   // column within the 256-wide part

    const int ty = tid >> 4;     // 0..15
    const int tx = tid & 15;     // 0..15

    // A-tile load mapping: 128 rows x 8 cols -> 256 float4 loads
    const int arow = tid >> 1;           // 0..127
    const int af4  = (tid & 1) * 4;      // 0 or 4
    // B-tile load mapping: 8 rows x 128 cols -> 256 float4 loads
    const int bk = tid >> 5;             // 0..7
    const int bc = (tid & 31) * 4;       // 0..124

    float acc[8][8];
    #pragma unroll
    for (int i = 0; i < 8; i++)
        #pragma unroll
        for (int j = 0; j < 8; j++) acc[i][j] = 0.0f;

    for (int k0 = 0; k0 < DD; k0 += BK) {
        // Load A tile (node rows), transposed into As[k][m]
        float4 av = make_float4(0.f, 0.f, 0.f, 0.f);
        const int gm = m0 + arow;
        if (gm < NNODES)
            av = *reinterpret_cast<const float4*>(node + (size_t)gm * DD + k0 + af4);
        As[af4 + 0][arow] = av.x;
        As[af4 + 1][arow] = av.y;
        As[af4 + 2][arow] = av.z;
        As[af4 + 3][arow] = av.w;

        // Load B tile from W
        float4 bv = *reinterpret_cast<const float4*>(
            W + (size_t)(wbase + k0 + bk) * DD + jcol + bc);
        *reinterpret_cast<float4*>(&Bs[bk][bc]) = bv;

        __syncthreads();

        #pragma unroll
        for (int k = 0; k < BK; k++) {
            float a[8], b[8];
            *reinterpret_cast<float4*>(a)     = *reinterpret_cast<float4*>(&As[k][ty * 8]);
            *reinterpret_cast<float4*>(a + 4) = *reinterpret_cast<float4*>(&As[k][ty * 8 + 4]);
            *reinterpret_cast<float4*>(b)     = *reinterpret_cast<float4*>(&Bs[k][tx * 8]);
            *reinterpret_cast<float4*>(b + 4) = *reinterpret_cast<float4*>(&Bs[k][tx * 8 + 4]);
            #pragma unroll
            for (int i = 0; i < 8; i++)
                #pragma unroll
                for (int j = 0; j < 8; j++)
                    acc[i][j] = fmaf(a[i], b[j], acc[i][j]);
        }
        __syncthreads();
    }

    // Store to g_proj [NNODES, 512]
    #pragma unroll
    for (int i = 0; i < 8; i++) {
        const int gm = m0 + ty * 8 + i;
        if (gm < NNODES) {
            float* dst = g_proj + (size_t)gm * 512 + n0 + tx * 8;
            *reinterpret_cast<float4*>(dst)     = *reinterpret_cast<float4*>(&acc[i][0]);
            *reinterpret_cast<float4*>(dst + 4) = *reinterpret_cast<float4*>(&acc[i][4]);
        }
    }
}

// ---------------------------------------------------------------------------
// Kernel B: edge GEMM + gather epilogue.
// out[e, j] = relu( edge[e,:] @ W[0:256, j] + proj[src[e], j]
//                   + proj[tgt[e], 256 + j] + b[j] )
// M=300000, N=256, K=256.
// ---------------------------------------------------------------------------
__global__ __launch_bounds__(256) void edge_update_kernel(
    const float* __restrict__ edge, const float* __restrict__ W,
    const int* __restrict__ src, const int* __restrict__ tgt,
    const float* __restrict__ bias, float* __restrict__ out)
{
    __shared__ float As[BK][BM];
    __shared__ float Bs[BK][BN];

    const int tid = threadIdx.x;
    const int m0  = blockIdx.y * BM;
    const int n0  = blockIdx.x * BN;     // 0 or 128

    const int ty = tid >> 4;
    const int tx = tid & 15;

    const int arow = tid >> 1;
    const int af4  = (tid & 1) * 4;
    const int bk = tid >> 5;
    const int bc = (tid & 31) * 4;

    float acc[8][8];
    #pragma unroll
    for (int i = 0; i < 8; i++)
        #pragma unroll
        for (int j = 0; j < 8; j++) acc[i][j] = 0.0f;

    for (int k0 = 0; k0 < DD; k0 += BK) {
        float4 av = make_float4(0.f, 0.f, 0.f, 0.f);
        const int gm = m0 + arow;
        if (gm < NEDGES)
            av = *reinterpret_cast<const float4*>(edge + (size_t)gm * DD + k0 + af4);
        As[af4 + 0][arow] = av.x;
        As[af4 + 1][arow] = av.y;
        As[af4 + 2][arow] = av.z;
        As[af4 + 3][arow] = av.w;

        float4 bv = *reinterpret_cast<const float4*>(
            W + (size_t)(k0 + bk) * DD + n0 + bc);
        *reinterpret_cast<float4*>(&Bs[bk][bc]) = bv;

        __syncthreads();

        #pragma unroll
        for (int k = 0; k < BK; k++) {
            float a[8], b[8];
            *reinterpret_cast<float4*>(a)     = *reinterpret_cast<float4*>(&As[k][ty * 8]);
            *reinterpret_cast<float4*>(a + 4) = *reinterpret_cast<float4*>(&As[k][ty * 8 + 4]);
            *reinterpret_cast<float4*>(b)     = *reinterpret_cast<float4*>(&Bs[k][tx * 8]);
            *reinterpret_cast<float4*>(b + 4) = *reinterpret_cast<float4*>(&Bs[k][tx * 8 + 4]);
            #pragma unroll
            for (int i = 0; i < 8; i++)
                #pragma unroll
                for (int j = 0; j < 8; j++)
                    acc[i][j] = fmaf(a[i], b[j], acc[i][j]);
        }
        __syncthreads();
    }

    // Epilogue: bias (fixed per-thread columns), gathered projections, relu.
    const int col = n0 + tx * 8;
    float4 bv0 = *reinterpret_cast<const float4*>(bias + col);
    float4 bv1 = *reinterpret_cast<const float4*>(bias + col + 4);

    #pragma unroll
    for (int i = 0; i < 8; i++) {
        const int gm = m0 + ty * 8 + i;
        if (gm < NEDGES) {
            const int s = src[gm];
            const int t = tgt[gm];
            const float* ps = g_proj + (size_t)s * 512 + col;        // src part
            const float* pt = g_proj + (size_t)t * 512 + 256 + col;  // tgt part
            float4 s0 = *reinterpret_cast<const float4*>(ps);
            float4 s1 = *reinterpret_cast<const float4*>(ps + 4);
            float4 t0 = *reinterpret_cast<const float4*>(pt);
            float4 t1 = *reinterpret_cast<const float4*>(pt + 4);

            float r[8];
            r[0] = acc[i][0] + s0.x + t0.x + bv0.x;
            r[1] = acc[i][1] + s0.y + t0.y + bv0.y;
            r[2] = acc[i][2] + s0.z + t0.z + bv0.z;
            r[3] = acc[i][3] + s0.w + t0.w + bv0.w;
            r[4] = acc[i][4] + s1.x + t1.x + bv1.x;
            r[5] = acc[i][5] + s1.y + t1.y + bv1.y;
            r[6] = acc[i][6] + s1.z + t1.z + bv1.z;
            r[7] = acc[i][7] + s1.w + t1.w + bv1.w;
            #pragma unroll
            for (int j = 0; j < 8; j++) r[j] = fmaxf(r[j], 0.0f);

            float* dst = out + (size_t)gm * DD + col;
            *reinterpret_cast<float4*>(dst)     = *reinterpret_cast<float4*>(&r[0]);
            *reinterpret_cast<float4*>(dst + 4) = *reinterpret_cast<float4*>(&r[4]);
        }
    }
}

extern "C" void kernel_launch(void* const* d_in, const int* in_sizes, int n_in,
                              void* d_out, int out_size)
{
    const float* edge_feat = (const float*)d_in[0];   // [300000, 256]
    const float* node_feat = (const float*)d_in[1];   // [50000, 256]
    const int*   src_idx   = (const int*)d_in[2];     // [300000]
    const int*   tgt_idx   = (const int*)d_in[3];     // [300000]
    const float* W         = (const float*)d_in[4];   // [768, 256]
    const float* b         = (const float*)d_in[5];   // [256]
    float* out = (float*)d_out;                       // [300000, 256]

    (void)in_sizes; (void)n_in; (void)out_size;

    // Kernel A: node projections [50000, 512]
    {
        dim3 grid(512 / BN, (NNODES + BM - 1) / BM);   // (4, 391)
        node_proj_kernel<<<grid, 256>>>(node_feat, W);
    }
    // Kernel B: edge GEMM + gather + relu
    {
        dim3 grid(DD / BN, (NEDGES + BM - 1) / BM);    // (2, 2344)
        edge_update_kernel<<<grid, 256>>>(edge_feat, W, src_idx, tgt_idx, b, out);
    }
}

// round 3
// speedup vs baseline: 1.4623x; 1.4623x over previous
#include <cuda_runtime.h>
#include <cuda_fp16.h>
#include <stdint.h>

#define DD      256
#define NNODES  50000
#define NEDGES  300000
#define SCALE     64.0f
#define INV_SCALE 0.015625f

// Device scratch (no runtime allocation allowed)
__device__ float  g_proj[(size_t)NNODES * 512];   // scaled by 64: [n][0:256)=src part, [256:512)=tgt part
__device__ __half g_Wh[256 * 768];                // Wt[n][k] = fp16(64 * W[k][n]), k in [0,768)

// ---------------------------------------------------------------------------
__global__ void prep_w(const float* __restrict__ W) {
    const int k = blockIdx.x;      // 0..767
    const int n = threadIdx.x;     // 0..255
    g_Wh[(size_t)n * 768 + k] = __float2half_rn(SCALE * W[(size_t)k * DD + n]);
}

// ---------------------------------------------------------------------------
__device__ __forceinline__ uint32_t smem_u32(const void* p) {
    uint32_t a;
    asm("{ .reg .u64 t; cvta.to.shared.u64 t, %1; cvt.u32.u64 %0, t; }" : "=r"(a) : "l"(p));
    return a;
}
__device__ __forceinline__ void ldsm4(uint32_t* r, uint32_t a) {
    asm volatile("ldmatrix.sync.aligned.m8n8.x4.shared.b16 {%0,%1,%2,%3}, [%4];"
                 : "=r"(r[0]), "=r"(r[1]), "=r"(r[2]), "=r"(r[3]) : "r"(a));
}
__device__ __forceinline__ void mma16816(float* d, const uint32_t* a, const uint32_t* b) {
    asm volatile("mma.sync.aligned.m16n8k16.row.col.f32.f16.f16.f32 "
                 "{%0,%1,%2,%3}, {%4,%5,%6,%7}, {%8,%9}, {%0,%1,%2,%3};"
                 : "+f"(d[0]), "+f"(d[1]), "+f"(d[2]), "+f"(d[3])
                 : "r"(a[0]), "r"(a[1]), "r"(a[2]), "r"(a[3]), "r"(b[0]), "r"(b[1]));
}

#define BSTR 264                              // halfs per B smem row (128B-row + pad)
#define ASTR 40                               // halfs per A smem row
#define B_HALFS (128 * BSTR)                  // 33792
#define A_HALFS (128 * ASTR)                  // 5120
#define SMEM_BYTES ((B_HALFS + 4 * A_HALFS) * 2)   // 108544 B

// MODE 0: proj = node @ [W1|W2] (scaled), M=50000, N=512 (4 n-blocks)
// MODE 1: out  = relu((edge@W0h + proj[src] + proj[tgt]) / 64 + b), M=300000, N=256 (2 n-blocks)
template <int MODE>
__global__ __launch_bounds__(256, 1)
void gemm_kernel(const float* __restrict__ Amat, const int* __restrict__ src,
                 const int* __restrict__ tgt, const float* __restrict__ bias,
                 float* __restrict__ out)
{
    constexpr int MTOT = (MODE == 0) ? NNODES : NEDGES;

    extern __shared__ __half sh[];
    __half* Bs = sh;
    auto As = [&](int buf, int part) { return sh + B_HALFS + (buf * 2 + part) * A_HALFS; };

    const int tid  = threadIdx.x;
    const int wid  = tid >> 5, lane = tid & 31;
    const int wm   = wid >> 1, wn = wid & 1;       // warp grid 4(m) x 2(n)
    const int m0   = blockIdx.x * 128;
    const int nb   = blockIdx.y;
    const int rowb = (MODE == 1) ? (nb * 128) : ((nb & 1) * 128);
    const int koff = (MODE == 1) ? 0 : (256 + (nb >> 1) * 256);
    const int ncol0 = nb * 128;

    // ---- load resident B tile: 128 n-rows x 256 k halfs ----
    {
        const int r  = tid >> 1;
        const int kh = (tid & 1) * 128;
        const uint4* s4 = (const uint4*)(g_Wh + (size_t)(rowb + r) * 768 + koff + kh);
        uint4* d4 = (uint4*)(Bs + r * BSTR + kh);
        #pragma unroll
        for (int i = 0; i < 16; i++) d4[i] = s4[i];
    }

    // ---- A streaming helpers ----
    const int ar  = tid >> 1;
    const int akq = (tid & 1) * 16;
    float4 pre[4];
    auto ldgA = [&](int c) {
        const int gm = m0 + ar;
        if (gm < MTOT) {
            const float4* p = (const float4*)(Amat + (size_t)gm * DD + c * 32 + akq);
            pre[0] = p[0]; pre[1] = p[1]; pre[2] = p[2]; pre[3] = p[3];
        } else {
            pre[0] = pre[1] = pre[2] = pre[3] = make_float4(0.f, 0.f, 0.f, 0.f);
        }
    };
    auto stsA = [&](int buf) {
        const float* f = (const float*)pre;
        uint32_t hu[8], lu[8];
        #pragma unroll
        for (int q = 0; q < 8; q++) {
            __half h0 = __float2half_rn(f[2 * q]);
            __half h1 = __float2half_rn(f[2 * q + 1]);
            __half l0 = __float2half_rn(f[2 * q]     - __half2float(h0));
            __half l1 = __float2half_rn(f[2 * q + 1] - __half2float(h1));
            hu[q] = ((uint32_t)__half_as_ushort(h1) << 16) | __half_as_ushort(h0);
            lu[q] = ((uint32_t)__half_as_ushort(l1) << 16) | __half_as_ushort(l0);
        }
        uint4* dh = (uint4*)(As(buf, 0) + ar * ASTR + akq);
        uint4* dl = (uint4*)(As(buf, 1) + ar * ASTR + akq);
        dh[0] = make_uint4(hu[0], hu[1], hu[2], hu[3]);
        dh[1] = make_uint4(hu[4], hu[5], hu[6], hu[7]);
        dl[0] = make_uint4(lu[0], lu[1], lu[2], lu[3]);
        dl[1] = make_uint4(lu[4], lu[5], lu[6], lu[7]);
    };

    // ---- ldmatrix base addresses ----
    uint32_t b_addr[4];
    {
        const int nrow = wn * 64 + (lane >> 4) * 8 + (lane & 7);
        const int kb   = ((lane >> 3) & 1) * 8;
        #pragma unroll
        for (int g = 0; g < 4; g++)
            b_addr[g] = smem_u32(Bs + (nrow + g * 16) * BSTR + kb);
    }
    uint32_t a_addr[2][2][2];   // [buf][part][m-tile]
    {
        const int arow = wm * 32 + (lane & 15);
        const int acb  = (lane >> 4) * 8;
        #pragma unroll
        for (int buf = 0; buf < 2; buf++)
            #pragma unroll
            for (int p = 0; p < 2; p++)
                #pragma unroll
                for (int i = 0; i < 2; i++)
                    a_addr[buf][p][i] = smem_u32(As(buf, p) + (arow + i * 16) * ASTR + acb);
    }

    float acc[2][8][4];
    #pragma unroll
    for (int i = 0; i < 2; i++)
        #pragma unroll
        for (int j = 0; j < 8; j++)
            #pragma unroll
            for (int q = 0; q < 4; q++) acc[i][j][q] = 0.f;

    // ---- pipeline: prefetch distance 2 ----
    ldgA(0); stsA(0);
    __syncthreads();
    ldgA(1);

    #pragma unroll 1
    for (int c = 0; c < 8; c++) {
        if (c < 7) stsA((c + 1) & 1);
        if (c < 6) ldgA(c + 2);
        __syncthreads();

        const int buf = c & 1;
        #pragma unroll
        for (int s = 0; s < 2; s++) {
            const uint32_t boff = (uint32_t)(c * 32 + s * 16) * 2;   // bytes
            uint32_t bf[4][4];
            #pragma unroll
            for (int g = 0; g < 4; g++) ldsm4(bf[g], b_addr[g] + boff);
            uint32_t ah[2][4], al[2][4];
            #pragma unroll
            for (int i = 0; i < 2; i++) ldsm4(ah[i], a_addr[buf][0][i] + s * 32);
            #pragma unroll
            for (int i = 0; i < 2; i++) ldsm4(al[i], a_addr[buf][1][i] + s * 32);

            #pragma unroll
            for (int i = 0; i < 2; i++)
                #pragma unroll
                for (int g = 0; g < 4; g++) {
                    mma16816(acc[i][2 * g],     ah[i], &bf[g][0]);
                    mma16816(acc[i][2 * g + 1], ah[i], &bf[g][2]);
                }
            #pragma unroll
            for (int i = 0; i < 2; i++)
                #pragma unroll
                for (int g = 0; g < 4; g++) {
                    mma16816(acc[i][2 * g],     al[i], &bf[g][0]);
                    mma16816(acc[i][2 * g + 1], al[i], &bf[g][2]);
                }
        }
        __syncthreads();
    }

    // ---- epilogue ----
    const int grp = lane >> 2, qc = (lane & 3) * 2;
    #pragma unroll
    for (int i = 0; i < 2; i++) {
        #pragma unroll
        for (int h = 0; h < 2; h++) {
            const int gm = m0 + wm * 32 + i * 16 + grp + h * 8;
            if (gm >= MTOT) continue;
            if (MODE == 0) {
                float* pp = g_proj + (size_t)gm * 512 + ncol0 + wn * 64;
                #pragma unroll
                for (int j = 0; j < 8; j++)
                    *(float2*)(pp + j * 8 + qc) =
                        make_float2(acc[i][j][2 * h], acc[i][j][2 * h + 1]);
            } else {
                const int si = src[gm], ti = tgt[gm];
                const float* ps = g_proj + (size_t)si * 512 + ncol0 + wn * 64;
                const float* pt = g_proj + (size_t)ti * 512 + 256 + ncol0 + wn * 64;
                const float* bb = bias + ncol0 + wn * 64;
                float* op = out + (size_t)gm * DD + ncol0 + wn * 64;
                #pragma unroll
                for (int j = 0; j < 8; j++) {
                    const int cc = j * 8 + qc;
                    float2 sv = *(const float2*)(ps + cc);
                    float2 tv = *(const float2*)(pt + cc);
                    float2 bv = *(const float2*)(bb + cc);
                    float x = fmaf(acc[i][j][2 * h]     + sv.x + tv.x, INV_SCALE, bv.x);
                    float y = fmaf(acc[i][j][2 * h + 1] + sv.y + tv.y, INV_SCALE, bv.y);
                    *(float2*)(op + cc) = make_float2(fmaxf(x, 0.f), fmaxf(y, 0.f));
                }
            }
        }
    }
}

// ---------------------------------------------------------------------------
extern "C" void kernel_launch(void* const* d_in, const int* in_sizes, int n_in,
                              void* d_out, int out_size)
{
    const float* edge_feat = (const float*)d_in[0];
    const float* node_feat = (const float*)d_in[1];
    const int*   src_idx   = (const int*)d_in[2];
    const int*   tgt_idx   = (const int*)d_in[3];
    const float* W         = (const float*)d_in[4];
    const float* b         = (const float*)d_in[5];
    float* out = (float*)d_out;
    (void)in_sizes; (void)n_in; (void)out_size;

    cudaFuncSetAttribute(gemm_kernel<0>, cudaFuncAttributeMaxDynamicSharedMemorySize, SMEM_BYTES);
    cudaFuncSetAttribute(gemm_kernel<1>, cudaFuncAttributeMaxDynamicSharedMemorySize, SMEM_BYTES);

    prep_w<<<768, 256>>>(W);
    gemm_kernel<0><<<dim3(391, 4),  256, SMEM_BYTES>>>(node_feat, nullptr, nullptr, nullptr, nullptr);
    gemm_kernel<1><<<dim3(2344, 2), 256, SMEM_BYTES>>>(edge_feat, src_idx, tgt_idx, b, out);
}

// round 4
// speedup vs baseline: 1.7024x; 1.1642x over previous
#include <cuda_runtime.h>
#include <cuda_fp16.h>
#include <stdint.h>

#define DD      256
#define NNODES  50000
#define NEDGES  300000
#define SCALE     64.0f
#define INV_SCALE 0.015625f

// Device scratch (no runtime allocation allowed)
__device__ float  g_proj[(size_t)NNODES * 512];   // scaled by 64: [n][0:256)=src part, [256:512)=tgt part
__device__ __half g_Wh[256 * 768];                // Wt[n][k] = fp16(64 * W[k][n]), k in [0,768)

// ---------------------------------------------------------------------------
__global__ void prep_w(const float* __restrict__ W) {
    const int k = blockIdx.x;      // 0..767
    const int n = threadIdx.x;     // 0..255
    g_Wh[(size_t)n * 768 + k] = __float2half_rn(SCALE * W[(size_t)k * DD + n]);
}

// ---------------------------------------------------------------------------
__device__ __forceinline__ uint32_t smem_u32(const void* p) {
    uint32_t a;
    asm("{ .reg .u64 t; cvta.to.shared.u64 t, %1; cvt.u32.u64 %0, t; }" : "=r"(a) : "l"(p));
    return a;
}
__device__ __forceinline__ void ldsm4(uint32_t* r, uint32_t a) {
    asm volatile("ldmatrix.sync.aligned.m8n8.x4.shared.b16 {%0,%1,%2,%3}, [%4];"
                 : "=r"(r[0]), "=r"(r[1]), "=r"(r[2]), "=r"(r[3]) : "r"(a));
}
__device__ __forceinline__ void mma16816(float* d, const uint32_t* a, const uint32_t* b) {
    asm volatile("mma.sync.aligned.m16n8k16.row.col.f32.f16.f16.f32 "
                 "{%0,%1,%2,%3}, {%4,%5,%6,%7}, {%8,%9}, {%0,%1,%2,%3};"
                 : "+f"(d[0]), "+f"(d[1]), "+f"(d[2]), "+f"(d[3])
                 : "r"(a[0]), "r"(a[1]), "r"(a[2]), "r"(a[3]), "r"(b[0]), "r"(b[1]));
}

#define BSTR 264                                   // halfs per B smem row (512B row + 16B pad)
#define ASTR 40                                    // halfs per A smem row
#define B_HALFS (256 * BSTR)                       // 67584
#define A_HALFS (128 * ASTR)                       // 5120
#define SMEM_BYTES ((B_HALFS + 2 * A_HALFS) * 2)   // 155648 B

// Single fp16 pass, BN=256 resident B tile.
// MODE 0: proj(scaled) = node @ [Wsrc|Wtgt]h, M=50000, N=512 (2 n-blocks of 256)
// MODE 1: out = relu((edge@W0h + proj[src] + proj[tgt]) * INV_SCALE + b), M=300000, N=256
template <int MODE>
__global__ __launch_bounds__(256, 1)
void gemm_kernel(const float* __restrict__ Amat, const int* __restrict__ src,
                 const int* __restrict__ tgt, const float* __restrict__ bias,
                 float* __restrict__ out)
{
    constexpr int MTOT = (MODE == 0) ? NNODES : NEDGES;

    extern __shared__ __half sh[];
    __half* Bs = sh;
    auto As = [&](int buf) { return sh + B_HALFS + buf * A_HALFS; };

    const int tid  = threadIdx.x;
    const int wid  = tid >> 5, lane = tid & 31;
    const int wm   = wid >> 1, wn = wid & 1;       // warp grid 4(m) x 2(n); warp tile 32 x 128
    const int m0   = blockIdx.x * 128;
    const int nb   = blockIdx.y;                   // 0..1 for MODE 0, 0 for MODE 1
    const int koff = (MODE == 0) ? (256 + nb * 256) : 0;

    // ---- load resident B tile: 256 n-rows x 256 k halfs ----
    {
        const uint4* s4 = (const uint4*)(g_Wh + (size_t)tid * 768 + koff);
        uint4* d4 = (uint4*)(Bs + tid * BSTR);
        #pragma unroll
        for (int i = 0; i < 32; i++) d4[i] = s4[i];
    }

    // ---- A streaming (chunk = 128 rows x 32 k floats) ----
    const int ar  = tid >> 1;
    const int akq = (tid & 1) * 16;
    float4 pre[4];
    auto ldgA = [&](int c) {
        const int gm = m0 + ar;
        if (gm < MTOT) {
            const float4* p = (const float4*)(Amat + (size_t)gm * DD + c * 32 + akq);
            pre[0] = p[0]; pre[1] = p[1]; pre[2] = p[2]; pre[3] = p[3];
        } else {
            pre[0] = pre[1] = pre[2] = pre[3] = make_float4(0.f, 0.f, 0.f, 0.f);
        }
    };
    auto stsA = [&](int buf) {
        const float* f = (const float*)pre;
        uint32_t hu[8];
        #pragma unroll
        for (int q = 0; q < 8; q++) {
            __half h0 = __float2half_rn(f[2 * q]);
            __half h1 = __float2half_rn(f[2 * q + 1]);
            hu[q] = ((uint32_t)__half_as_ushort(h1) << 16) | __half_as_ushort(h0);
        }
        uint4* dh = (uint4*)(As(buf) + ar * ASTR + akq);
        dh[0] = make_uint4(hu[0], hu[1], hu[2], hu[3]);
        dh[1] = make_uint4(hu[4], hu[5], hu[6], hu[7]);
    };

    // ---- ldmatrix base addresses ----
    uint32_t b_addr[8];
    {
        const int nrow = wn * 128 + (lane >> 4) * 8 + (lane & 7);
        const int kb   = ((lane >> 3) & 1) * 8;
        #pragma unroll
        for (int g = 0; g < 8; g++)
            b_addr[g] = smem_u32(Bs + (nrow + g * 16) * BSTR + kb);
    }
    uint32_t a_addr[2][2];   // [buf][m-tile]
    {
        const int arow = wm * 32 + (lane & 15);
        const int acb  = (lane >> 4) * 8;
        #pragma unroll
        for (int buf = 0; buf < 2; buf++)
            #pragma unroll
            for (int i = 0; i < 2; i++)
                a_addr[buf][i] = smem_u32(As(buf) + (arow + i * 16) * ASTR + acb);
    }

    float acc[2][16][4];
    #pragma unroll
    for (int i = 0; i < 2; i++)
        #pragma unroll
        for (int j = 0; j < 16; j++)
            #pragma unroll
            for (int q = 0; q < 4; q++) acc[i][j][q] = 0.f;

    // ---- pipeline: prefetch distance 2 ----
    ldgA(0); stsA(0);
    __syncthreads();
    ldgA(1);

    #pragma unroll 1
    for (int c = 0; c < 8; c++) {
        if (c < 7) stsA((c + 1) & 1);
        if (c < 6) ldgA(c + 2);
        __syncthreads();

        const int buf = c & 1;
        #pragma unroll
        for (int s = 0; s < 2; s++) {
            const uint32_t boff = (uint32_t)(c * 32 + s * 16) * 2;   // bytes
            uint32_t ah[2][4];
            #pragma unroll
            for (int i = 0; i < 2; i++) ldsm4(ah[i], a_addr[buf][i] + s * 32);
            #pragma unroll
            for (int g = 0; g < 8; g++) {
                uint32_t bf[4];
                ldsm4(bf, b_addr[g] + boff);
                mma16816(acc[0][2 * g],     ah[0], &bf[0]);
                mma16816(acc[0][2 * g + 1], ah[0], &bf[2]);
                mma16816(acc[1][2 * g],     ah[1], &bf[0]);
                mma16816(acc[1][2 * g + 1], ah[1], &bf[2]);
            }
        }
        __syncthreads();
    }

    // ---- epilogue (warp covers cols wn*128 .. wn*128+127) ----
    const int grp = lane >> 2, qc = (lane & 3) * 2;
    const int colw = wn * 128;
    #pragma unroll
    for (int i = 0; i < 2; i++) {
        #pragma unroll
        for (int h = 0; h < 2; h++) {
            const int gm = m0 + wm * 32 + i * 16 + grp + h * 8;
            if (gm >= MTOT) continue;
            if (MODE == 0) {
                float* pp = g_proj + (size_t)gm * 512 + nb * 256 + colw;
                #pragma unroll
                for (int j = 0; j < 16; j++)
                    *(float2*)(pp + j * 8 + qc) =
                        make_float2(acc[i][j][2 * h], acc[i][j][2 * h + 1]);
            } else {
                const int si = src[gm], ti = tgt[gm];
                const float* ps = g_proj + (size_t)si * 512 + colw;
                const float* pt = g_proj + (size_t)ti * 512 + 256 + colw;
                const float* bb = bias + colw;
                float* op = out + (size_t)gm * DD + colw;
                #pragma unroll
                for (int j = 0; j < 16; j++) {
                    const int cc = j * 8 + qc;
                    float2 sv = *(const float2*)(ps + cc);
                    float2 tv = *(const float2*)(pt + cc);
                    float2 bv = *(const float2*)(bb + cc);
                    float x = fmaf(acc[i][j][2 * h]     + sv.x + tv.x, INV_SCALE, bv.x);
                    float y = fmaf(acc[i][j][2 * h + 1] + sv.y + tv.y, INV_SCALE, bv.y);
                    *(float2*)(op + cc) = make_float2(fmaxf(x, 0.f), fmaxf(y, 0.f));
                }
            }
        }
    }
}

// ---------------------------------------------------------------------------
extern "C" void kernel_launch(void* const* d_in, const int* in_sizes, int n_in,
                              void* d_out, int out_size)
{
    const float* edge_feat = (const float*)d_in[0];
    const float* node_feat = (const float*)d_in[1];
    const int*   src_idx   = (const int*)d_in[2];
    const int*   tgt_idx   = (const int*)d_in[3];
    const float* W         = (const float*)d_in[4];
    const float* b         = (const float*)d_in[5];
    float* out = (float*)d_out;
    (void)in_sizes; (void)n_in; (void)out_size;

    cudaFuncSetAttribute(gemm_kernel<0>, cudaFuncAttributeMaxDynamicSharedMemorySize, SMEM_BYTES);
    cudaFuncSetAttribute(gemm_kernel<1>, cudaFuncAttributeMaxDynamicSharedMemorySize, SMEM_BYTES);

    prep_w<<<768, 256>>>(W);
    gemm_kernel<0><<<dim3(391, 2),  256, SMEM_BYTES>>>(node_feat, nullptr, nullptr, nullptr, nullptr);
    gemm_kernel<1><<<dim3(2344, 1), 256, SMEM_BYTES>>>(edge_feat, src_idx, tgt_idx, b, out);
}

// round 5
// speedup vs baseline: 2.4781x; 1.4557x over previous
#include <cuda_runtime.h>
#include <cuda_fp16.h>
#include <stdint.h>

#define DD      256
#define NNODES  50000
#define NEDGES  300000
#define SCALE     64.0f
#define INV_SCALE 0.015625f

// Device scratch (no runtime allocation allowed)
__device__ float  g_proj[(size_t)NNODES * 512];   // scaled by 64: [n][0:256)=src, [256:512)=tgt
__device__ __half g_Wh[256 * 768];                // Wt[n][k] = fp16(64 * W[k][n])

// ---------------------------------------------------------------------------
__global__ void prep_w(const float* __restrict__ W) {
    const int k = blockIdx.x;      // 0..767
    const int n = threadIdx.x;     // 0..255
    g_Wh[(size_t)n * 768 + k] = __float2half_rn(SCALE * W[(size_t)k * DD + n]);
}

// ---------------------------------------------------------------------------
__device__ __forceinline__ uint32_t smem_u32(const void* p) {
    uint32_t a;
    asm("{ .reg .u64 t; cvta.to.shared.u64 t, %1; cvt.u32.u64 %0, t; }" : "=r"(a) : "l"(p));
    return a;
}
__device__ __forceinline__ void ldsm4(uint32_t* r, uint32_t a) {
    asm volatile("ldmatrix.sync.aligned.m8n8.x4.shared.b16 {%0,%1,%2,%3}, [%4];"
                 : "=r"(r[0]), "=r"(r[1]), "=r"(r[2]), "=r"(r[3]) : "r"(a));
}
__device__ __forceinline__ void mma16816(float* d, const uint32_t* a, const uint32_t* b) {
    asm volatile("mma.sync.aligned.m16n8k16.row.col.f32.f16.f16.f32 "
                 "{%0,%1,%2,%3}, {%4,%5,%6,%7}, {%8,%9}, {%0,%1,%2,%3};"
                 : "+f"(d[0]), "+f"(d[1]), "+f"(d[2]), "+f"(d[3])
                 : "r"(a[0]), "r"(a[1]), "r"(a[2]), "r"(a[3]), "r"(b[0]), "r"(b[1]));
}

#define NTHR 512
#define BSTR 264                                   // halfs per B smem row (+pad)
#define ASTR 40                                    // halfs per A smem row
#define B_HALFS (256 * BSTR)                       // 67584
#define A_HALFS (128 * ASTR)                       // 5120
#define SMEM_BYTES ((B_HALFS + 2 * A_HALFS) * 2)   // 155648 B

// 512 threads, warp grid 4(m) x 4(n), warp tile 32 x 64. BM=128, BN=256.
// MODE 0: proj(scaled) = node @ [Wsrc|Wtgt]h, M=50000, N=512 (2 n-blocks of 256)
// MODE 1: out = relu((edge@W0h + proj[src] + proj[tgt]) * INV_SCALE + b), M=300000, N=256
template <int MODE>
__global__ __launch_bounds__(NTHR, 1)
void gemm_kernel(const float* __restrict__ Amat, const int* __restrict__ src,
                 const int* __restrict__ tgt, const float* __restrict__ bias,
                 float* __restrict__ out)
{
    constexpr int MTOT = (MODE == 0) ? NNODES : NEDGES;

    extern __shared__ __half sh[];
    __half* Bs = sh;
    auto As = [&](int buf) { return sh + B_HALFS + buf * A_HALFS; };

    const int tid  = threadIdx.x;
    const int wid  = tid >> 5, lane = tid & 31;
    const int wm   = wid >> 2, wn = wid & 3;       // 4m x 4n; warp tile 32 x 64
    const int m0   = blockIdx.x * 128;
    const int nb   = blockIdx.y;
    const int koff = (MODE == 0) ? (256 + nb * 256) : 0;

    // ---- load resident B tile: 256 n-rows x 256 k halfs (512 thr: 128 halfs each) ----
    {
        const int r  = tid >> 1;
        const int kh = (tid & 1) * 128;
        const uint4* s4 = (const uint4*)(g_Wh + (size_t)r * 768 + koff + kh);
        uint4* d4 = (uint4*)(Bs + r * BSTR + kh);
        #pragma unroll
        for (int i = 0; i < 16; i++) d4[i] = s4[i];
    }

    // ---- A streaming (chunk = 128 rows x 32 k floats; 8 floats/thread) ----
    const int ar  = tid >> 2;
    const int akq = (tid & 3) * 8;
    float4 pre[2];
    auto ldgA = [&](int c) {
        const int gm = m0 + ar;
        if (gm < MTOT) {
            const float4* p = (const float4*)(Amat + (size_t)gm * DD + c * 32 + akq);
            pre[0] = p[0]; pre[1] = p[1];
        } else {
            pre[0] = pre[1] = make_float4(0.f, 0.f, 0.f, 0.f);
        }
    };
    auto stsA = [&](int buf) {
        const float* f = (const float*)pre;
        uint32_t hu[4];
        #pragma unroll
        for (int q = 0; q < 4; q++) {
            __half h0 = __float2half_rn(f[2 * q]);
            __half h1 = __float2half_rn(f[2 * q + 1]);
            hu[q] = ((uint32_t)__half_as_ushort(h1) << 16) | __half_as_ushort(h0);
        }
        *(uint4*)(As(buf) + ar * ASTR + akq) = make_uint4(hu[0], hu[1], hu[2], hu[3]);
    };

    // ---- ldmatrix base addresses ----
    uint32_t b_addr[4];
    {
        const int nrow = wn * 64 + (lane >> 4) * 8 + (lane & 7);
        const int kb   = ((lane >> 3) & 1) * 8;
        #pragma unroll
        for (int g = 0; g < 4; g++)
            b_addr[g] = smem_u32(Bs + (nrow + g * 16) * BSTR + kb);
    }
    uint32_t a_addr[2][2];   // [buf][m-tile]
    {
        const int arow = wm * 32 + (lane & 15);
        const int acb  = (lane >> 4) * 8;
        #pragma unroll
        for (int buf = 0; buf < 2; buf++)
            #pragma unroll
            for (int i = 0; i < 2; i++)
                a_addr[buf][i] = smem_u32(As(buf) + (arow + i * 16) * ASTR + acb);
    }

    float acc[2][8][4];
    #pragma unroll
    for (int i = 0; i < 2; i++)
        #pragma unroll
        for (int j = 0; j < 8; j++)
            #pragma unroll
            for (int q = 0; q < 4; q++) acc[i][j][q] = 0.f;

    // ---- pipeline: prefetch distance 2 ----
    ldgA(0); stsA(0);
    __syncthreads();
    ldgA(1);

    #pragma unroll 1
    for (int c = 0; c < 8; c++) {
        if (c < 7) stsA((c + 1) & 1);
        if (c < 6) ldgA(c + 2);
        __syncthreads();

        const int buf = c & 1;
        #pragma unroll
        for (int s = 0; s < 2; s++) {
            const uint32_t boff = (uint32_t)(c * 32 + s * 16) * 2;   // bytes
            uint32_t ah[2][4];
            #pragma unroll
            for (int i = 0; i < 2; i++) ldsm4(ah[i], a_addr[buf][i] + s * 32);
            #pragma unroll
            for (int g = 0; g < 4; g++) {
                uint32_t bf[4];
                ldsm4(bf, b_addr[g] + boff);
                mma16816(acc[0][2 * g],     ah[0], &bf[0]);
                mma16816(acc[0][2 * g + 1], ah[0], &bf[2]);
                mma16816(acc[1][2 * g],     ah[1], &bf[0]);
                mma16816(acc[1][2 * g + 1], ah[1], &bf[2]);
            }
        }
        __syncthreads();
    }

    // ---- epilogue (warp covers cols wn*64 .. wn*64+63) ----
    const int grp = lane >> 2, qc = (lane & 3) * 2;
    const int colw = wn * 64;
    #pragma unroll
    for (int i = 0; i < 2; i++) {
        #pragma unroll
        for (int h = 0; h < 2; h++) {
            const int gm = m0 + wm * 32 + i * 16 + grp + h * 8;
            if (gm >= MTOT) continue;
            if (MODE == 0) {
                float* pp = g_proj + (size_t)gm * 512 + nb * 256 + colw;
                #pragma unroll
                for (int j = 0; j < 8; j++)
                    *(float2*)(pp + j * 8 + qc) =
                        make_float2(acc[i][j][2 * h], acc[i][j][2 * h + 1]);
            } else {
                const int si = src[gm], ti = tgt[gm];
                const float* ps = g_proj + (size_t)si * 512 + colw;
                const float* pt = g_proj + (size_t)ti * 512 + 256 + colw;
                const float* bb = bias + colw;
                float* op = out + (size_t)gm * DD + colw;
                #pragma unroll
                for (int j = 0; j < 8; j++) {
                    const int cc = j * 8 + qc;
                    float2 sv = *(const float2*)(ps + cc);
                    float2 tv = *(const float2*)(pt + cc);
                    float2 bv = *(const float2*)(bb + cc);
                    float x = fmaf(acc[i][j][2 * h]     + sv.x + tv.x, INV_SCALE, bv.x);
                    float y = fmaf(acc[i][j][2 * h + 1] + sv.y + tv.y, INV_SCALE, bv.y);
                    *(float2*)(op + cc) = make_float2(fmaxf(x, 0.f), fmaxf(y, 0.f));
                }
            }
        }
    }
}

// ---------------------------------------------------------------------------
extern "C" void kernel_launch(void* const* d_in, const int* in_sizes, int n_in,
                              void* d_out, int out_size)
{
    const float* edge_feat = (const float*)d_in[0];
    const float* node_feat = (const float*)d_in[1];
    const int*   src_idx   = (const int*)d_in[2];
    const int*   tgt_idx   = (const int*)d_in[3];
    const float* W         = (const float*)d_in[4];
    const float* b         = (const float*)d_in[5];
    float* out = (float*)d_out;
    (void)in_sizes; (void)n_in; (void)out_size;

    cudaFuncSetAttribute(gemm_kernel<0>, cudaFuncAttributeMaxDynamicSharedMemorySize, SMEM_BYTES);
    cudaFuncSetAttribute(gemm_kernel<1>, cudaFuncAttributeMaxDynamicSharedMemorySize, SMEM_BYTES);

    prep_w<<<768, 256>>>(W);
    gemm_kernel<0><<<dim3(391, 2),  NTHR, SMEM_BYTES>>>(node_feat, nullptr, nullptr, nullptr, nullptr);
    gemm_kernel<1><<<dim3(2344, 1), NTHR, SMEM_BYTES>>>(edge_feat, src_idx, tgt_idx, b, out);
}

// round 6
// speedup vs baseline: 2.5343x; 1.0227x over previous
#include <cuda_runtime.h>
#include <cuda_fp16.h>
#include <stdint.h>

#define DD      256
#define NNODES  50000
#define NEDGES  300000
#define SCALE     64.0f
#define INV_SCALE 0.015625f

// Device scratch (no runtime allocation allowed)
__device__ float  g_proj[(size_t)NNODES * 512];   // scaled by 64: [n][0:256)=src, [256:512)=tgt
__device__ __half g_Wh[256 * 768];                // Wt[n][k] = fp16(64 * W[k][n])

// ---------------------------------------------------------------------------
__global__ void prep_w(const float* __restrict__ W) {
    const int k = blockIdx.x;      // 0..767
    const int n = threadIdx.x;     // 0..255
    g_Wh[(size_t)n * 768 + k] = __float2half_rn(SCALE * W[(size_t)k * DD + n]);
}

// ---------------------------------------------------------------------------
__device__ __forceinline__ uint32_t smem_u32(const void* p) {
    uint32_t a;
    asm("{ .reg .u64 t; cvta.to.shared.u64 t, %1; cvt.u32.u64 %0, t; }" : "=r"(a) : "l"(p));
    return a;
}
__device__ __forceinline__ void ldsm4(uint32_t* r, uint32_t a) {
    asm volatile("ldmatrix.sync.aligned.m8n8.x4.shared.b16 {%0,%1,%2,%3}, [%4];"
                 : "=r"(r[0]), "=r"(r[1]), "=r"(r[2]), "=r"(r[3]) : "r"(a));
}
__device__ __forceinline__ void mma16816(float* d, const uint32_t* a, const uint32_t* b) {
    asm volatile("mma.sync.aligned.m16n8k16.row.col.f32.f16.f16.f32 "
                 "{%0,%1,%2,%3}, {%4,%5,%6,%7}, {%8,%9}, {%0,%1,%2,%3};"
                 : "+f"(d[0]), "+f"(d[1]), "+f"(d[2]), "+f"(d[3])
                 : "r"(a[0]), "r"(a[1]), "r"(a[2]), "r"(a[3]), "r"(b[0]), "r"(b[1]));
}

#define NTHR 512
#define BSTR 264                                   // halfs per B smem row (+pad)
#define ASTR 40                                    // halfs per A smem row
#define B_HALFS (256 * BSTR)                       // 67584
#define A_HALFS (128 * ASTR)                       // 5120
#define SMEM_BYTES ((B_HALFS + 3 * A_HALFS) * 2)   // 165888 B

// 512 threads, warp grid 4(m) x 4(n), warp tile 32 x 64. BM=128, BN=256.
// 3-stage A ring => exactly ONE __syncthreads per K-chunk.
// MODE 0: proj(scaled) = node @ [Wsrc|Wtgt]h, M=50000, N=512 (2 n-blocks of 256)
// MODE 1: out = relu((edge@W0h + proj[src] + proj[tgt]) * INV_SCALE + b), M=300000, N=256
template <int MODE>
__global__ __launch_bounds__(NTHR, 1)
void gemm_kernel(const float* __restrict__ Amat, const int* __restrict__ src,
                 const int* __restrict__ tgt, const float* __restrict__ bias,
                 float* __restrict__ out)
{
    constexpr int MTOT = (MODE == 0) ? NNODES : NEDGES;

    extern __shared__ __half sh[];
    __half* Bs = sh;
    auto As = [&](int buf) { return sh + B_HALFS + buf * A_HALFS; };

    const int tid  = threadIdx.x;
    const int wid  = tid >> 5, lane = tid & 31;
    const int wm   = wid >> 2, wn = wid & 3;       // 4m x 4n; warp tile 32 x 64
    const int m0   = blockIdx.x * 128;
    const int nb   = blockIdx.y;
    const int koff = (MODE == 0) ? (256 + nb * 256) : 0;

    // ---- load resident B tile: 256 n-rows x 256 k halfs (512 thr: 128 halfs each) ----
    {
        const int r  = tid >> 1;
        const int kh = (tid & 1) * 128;
        const uint4* s4 = (const uint4*)(g_Wh + (size_t)r * 768 + koff + kh);
        uint4* d4 = (uint4*)(Bs + r * BSTR + kh);
        #pragma unroll
        for (int i = 0; i < 16; i++) d4[i] = s4[i];
    }

    // ---- A streaming (chunk = 128 rows x 32 k floats; 8 floats/thread) ----
    const int ar  = tid >> 2;
    const int akq = (tid & 3) * 8;
    float4 pre[2];
    auto ldgA = [&](int c) {
        const int gm = m0 + ar;
        if (gm < MTOT) {
            const float4* p = (const float4*)(Amat + (size_t)gm * DD + c * 32 + akq);
            pre[0] = p[0]; pre[1] = p[1];
        } else {
            pre[0] = pre[1] = make_float4(0.f, 0.f, 0.f, 0.f);
        }
    };
    auto stsA = [&](int buf) {
        const float* f = (const float*)pre;
        uint32_t hu[4];
        #pragma unroll
        for (int q = 0; q < 4; q++) {
            __half h0 = __float2half_rn(f[2 * q]);
            __half h1 = __float2half_rn(f[2 * q + 1]);
            hu[q] = ((uint32_t)__half_as_ushort(h1) << 16) | __half_as_ushort(h0);
        }
        *(uint4*)(As(buf) + ar * ASTR + akq) = make_uint4(hu[0], hu[1], hu[2], hu[3]);
    };

    // ---- ldmatrix base addresses ----
    uint32_t b_addr[4];
    {
        const int nrow = wn * 64 + (lane >> 4) * 8 + (lane & 7);
        const int kb   = ((lane >> 3) & 1) * 8;
        #pragma unroll
        for (int g = 0; g < 4; g++)
            b_addr[g] = smem_u32(Bs + (nrow + g * 16) * BSTR + kb);
    }
    uint32_t a_base;   // per-buffer offset added at use
    {
        const int arow = wm * 32 + (lane & 15);
        const int acb  = (lane >> 4) * 8;
        a_base = smem_u32(As(0) + arow * ASTR + acb);
    }

    float acc[2][8][4];
    #pragma unroll
    for (int i = 0; i < 2; i++)
        #pragma unroll
        for (int j = 0; j < 8; j++)
            #pragma unroll
            for (int q = 0; q < 4; q++) acc[i][j][q] = 0.f;

    // ---- prologue: fill stage 0, prefetch stage 1 ----
    ldgA(0); stsA(0); ldgA(1);
    __syncthreads();

    // ---- mainloop: ONE sync per chunk (3-stage ring) ----
    #pragma unroll 1
    for (int c = 0; c < 8; c++) {
        if (c < 7) stsA((c + 1) % 3);
        if (c < 6) ldgA(c + 2);

        const uint32_t abuf = a_base + (uint32_t)((c % 3) * A_HALFS * 2);
        const uint32_t boff = (uint32_t)(c * 64);   // bytes: c*32 halfs

        #pragma unroll
        for (int s = 0; s < 2; s++) {
            // batch-issue all loads for this s-step, then all MMAs
            uint32_t ah[2][4], bf[4][4];
            ldsm4(ah[0], abuf + s * 32);
            ldsm4(ah[1], abuf + 16 * ASTR * 2 + s * 32);
            #pragma unroll
            for (int g = 0; g < 4; g++) ldsm4(bf[g], b_addr[g] + boff + s * 32);

            #pragma unroll
            for (int g = 0; g < 4; g++) {
                mma16816(acc[0][2 * g],     ah[0], &bf[g][0]);
                mma16816(acc[0][2 * g + 1], ah[0], &bf[g][2]);
                mma16816(acc[1][2 * g],     ah[1], &bf[g][0]);
                mma16816(acc[1][2 * g + 1], ah[1], &bf[g][2]);
            }
        }
        __syncthreads();
    }

    // ---- epilogue (warp covers cols wn*64 .. wn*64+63) ----
    const int grp = lane >> 2, qc = (lane & 3) * 2;
    const int colw = wn * 64;
    #pragma unroll
    for (int i = 0; i < 2; i++) {
        #pragma unroll
        for (int h = 0; h < 2; h++) {
            const int gm = m0 + wm * 32 + i * 16 + grp + h * 8;
            if (gm >= MTOT) continue;
            if (MODE == 0) {
                float* pp = g_proj + (size_t)gm * 512 + nb * 256 + colw;
                #pragma unroll
                for (int j = 0; j < 8; j++)
                    *(float2*)(pp + j * 8 + qc) =
                        make_float2(acc[i][j][2 * h], acc[i][j][2 * h + 1]);
            } else {
                const int si = src[gm], ti = tgt[gm];
                const float* ps = g_proj + (size_t)si * 512 + colw;
                const float* pt = g_proj + (size_t)ti * 512 + 256 + colw;
                const float* bb = bias + colw;
                float* op = out + (size_t)gm * DD + colw;
                #pragma unroll
                for (int j = 0; j < 8; j++) {
                    const int cc = j * 8 + qc;
                    float2 sv = *(const float2*)(ps + cc);
                    float2 tv = *(const float2*)(pt + cc);
                    float2 bv = *(const float2*)(bb + cc);
                    float x = fmaf(acc[i][j][2 * h]     + sv.x + tv.x, INV_SCALE, bv.x);
                    float y = fmaf(acc[i][j][2 * h + 1] + sv.y + tv.y, INV_SCALE, bv.y);
                    *(float2*)(op + cc) = make_float2(fmaxf(x, 0.f), fmaxf(y, 0.f));
                }
            }
        }
    }
}

// ---------------------------------------------------------------------------
extern "C" void kernel_launch(void* const* d_in, const int* in_sizes, int n_in,
                              void* d_out, int out_size)
{
    const float* edge_feat = (const float*)d_in[0];
    const float* node_feat = (const float*)d_in[1];
    const int*   src_idx   = (const int*)d_in[2];
    const int*   tgt_idx   = (const int*)d_in[3];
    const float* W         = (const float*)d_in[4];
    const float* b         = (const float*)d_in[5];
    float* out = (float*)d_out;
    (void)in_sizes; (void)n_in; (void)out_size;

    cudaFuncSetAttribute(gemm_kernel<0>, cudaFuncAttributeMaxDynamicSharedMemorySize, SMEM_BYTES);
    cudaFuncSetAttribute(gemm_kernel<1>, cudaFuncAttributeMaxDynamicSharedMemorySize, SMEM_BYTES);

    prep_w<<<768, 256>>>(W);
    gemm_kernel<0><<<dim3(391, 2),  NTHR, SMEM_BYTES>>>(node_feat, nullptr, nullptr, nullptr, nullptr);
    gemm_kernel<1><<<dim3(2344, 1), NTHR, SMEM_BYTES>>>(edge_feat, src_idx, tgt_idx, b, out);
}